// round 10
// baseline (speedup 1.0000x reference)
#include <cuda_runtime.h>
#include <cstdint>

#define N_MAX 100000
#define E_MAX 1250000

// ---------------- scratch (static device allocations; no runtime alloc) -----
__device__ int   g_is64;
__device__ int   g_deg[N_MAX];
__device__ int   g_incl[N_MAX];
__device__ int   g_rowptr[N_MAX];
__device__ int   g_cursor[N_MAX];
__device__ int   g_bsum[256];
__device__ float g_dinv[N_MAX];   // rsqrt(indeg+1)  (GCN)
__device__ float g_cinv[N_MAX];   // 1/max(indeg,1)  (SAGE mean)
__device__ int   g_edge[E_MAX];   // src index, bucketed by dst
__device__ float g_buf[6][(size_t)N_MAX * 64];

// ---------------- fused: zero degrees + edge-dtype detection ----------------
__global__ void k_detzero(const void* __restrict__ ei, int e, int n) {
    int i = blockIdx.x * blockDim.x + threadIdx.x;
    if (i < n) g_deg[i] = 0;
    if (blockIdx.x == 0) {
        __shared__ int bad;
        if (threadIdx.x == 0) bad = 0;
        __syncthreads();
        const long long* p = (const long long*)ei;
        int m = e < 2048 ? e : 2048;
        for (int j = threadIdx.x; j < m; j += blockDim.x) {
            long long v = p[j];
            if (v < 0 || v >= (long long)n) bad = 1;
        }
        __syncthreads();
        if (threadIdx.x == 0) g_is64 = bad ? 0 : 1;
    }
}

__device__ __forceinline__ int ld_idx(const void* __restrict__ ei, int is64,
                                      long long pos, int n) {
    long long v = is64 ? ((const long long*)ei)[pos]
                       : (long long)((const int*)ei)[pos];
    int s = (int)v;
    if ((unsigned)s >= (unsigned)n) s = 0;   // trap-safety clamp
    return s;
}

// ---------------- CSR build --------------------------------------------------
__global__ void k_count(const void* __restrict__ ei, int e, int n) {
    int i = blockIdx.x * blockDim.x + threadIdx.x;
    if (i >= e) return;
    int is64 = g_is64;
    int d = ld_idx(ei, is64, (long long)e + i, n);
    atomicAdd(&g_deg[d], 1);
}

__global__ void k_scan1(int n) {  // per-block inclusive scan (1024/block)
    __shared__ int sh[1024];
    int t = threadIdx.x;
    int i = blockIdx.x * 1024 + t;
    int v = (i < n) ? g_deg[i] : 0;
    sh[t] = v;
    __syncthreads();
    for (int off = 1; off < 1024; off <<= 1) {
        int add = (t >= off) ? sh[t - off] : 0;
        __syncthreads();
        sh[t] += add;
        __syncthreads();
    }
    if (i < n) g_incl[i] = sh[t];
    if (t == 1023) g_bsum[blockIdx.x] = sh[1023];
}

// fused scan2+scan3: every block redundantly scans the <=256 block sums in smem
__global__ void k_scan23(int n, int nb) {
    __shared__ int sh[256];
    __shared__ int orig[256];
    int t = threadIdx.x;
    if (t < 256) {
        int v = (t < nb) ? g_bsum[t] : 0;
        sh[t] = v;
        orig[t] = v;
    }
    __syncthreads();
    for (int off = 1; off < 256; off <<= 1) {
        int add = (t < 256 && t >= off) ? sh[t - off] : 0;
        __syncthreads();
        if (t < 256) sh[t] += add;
        __syncthreads();
    }
    int i = blockIdx.x * 1024 + t;
    if (i >= n) return;
    int boff = sh[blockIdx.x] - orig[blockIdx.x];  // exclusive prefix of this block
    int d  = g_deg[i];
    int rp = g_incl[i] - d + boff;
    g_rowptr[i] = rp;
    g_cursor[i] = rp;
    g_dinv[i] = rsqrtf((float)d + 1.0f);
    g_cinv[i] = 1.0f / fmaxf((float)d, 1.0f);
}

__global__ void k_scatter(const void* __restrict__ ei, int e, int n) {
    int i = blockIdx.x * blockDim.x + threadIdx.x;
    if (i >= e) return;
    int is64 = g_is64;
    int s = ld_idx(ei, is64, i, n);
    int d = ld_idx(ei, is64, (long long)e + i, n);
    int pos = atomicAdd(&g_cursor[d], 1);
    g_edge[pos] = s;
}

// ---------------- fused dual aggregations (warp per node, 2 feats/lane) -----
// Unrolled x4 with independent gathers for MLP.
__global__ void k_agg_dual1(const float* __restrict__ x,
                            float* __restrict__ outG, float* __restrict__ outM, int n) {
    int gw   = (blockIdx.x * blockDim.x + threadIdx.x) >> 5;
    int lane = threadIdx.x & 31;
    if (gw >= n) return;
    int start = g_rowptr[gw];
    int cnt   = g_deg[gw];
    float wx = 0.f, wy = 0.f, mx = 0.f, my = 0.f;
    int e = 0;
    for (; e + 4 <= cnt; e += 4) {
        int i0 = g_edge[start + e];
        int i1 = g_edge[start + e + 1];
        int i2 = g_edge[start + e + 2];
        int i3 = g_edge[start + e + 3];
        float d0 = g_dinv[i0], d1 = g_dinv[i1], d2 = g_dinv[i2], d3 = g_dinv[i3];
        float2 v0 = *(const float2*)(x + (size_t)i0 * 64 + lane * 2);
        float2 v1 = *(const float2*)(x + (size_t)i1 * 64 + lane * 2);
        float2 v2 = *(const float2*)(x + (size_t)i2 * 64 + lane * 2);
        float2 v3 = *(const float2*)(x + (size_t)i3 * 64 + lane * 2);
        wx = fmaf(d0, v0.x, fmaf(d1, v1.x, fmaf(d2, v2.x, fmaf(d3, v3.x, wx))));
        wy = fmaf(d0, v0.y, fmaf(d1, v1.y, fmaf(d2, v2.y, fmaf(d3, v3.y, wy))));
        mx += v0.x + v1.x + v2.x + v3.x;
        my += v0.y + v1.y + v2.y + v3.y;
    }
    for (; e < cnt; e++) {
        int i0 = g_edge[start + e];
        float d0 = g_dinv[i0];
        float2 v0 = *(const float2*)(x + (size_t)i0 * 64 + lane * 2);
        wx = fmaf(d0, v0.x, wx);
        wy = fmaf(d0, v0.y, wy);
        mx += v0.x;
        my += v0.y;
    }
    float dd = g_dinv[gw];
    float ci = g_cinv[gw];
    float2 xv = *(const float2*)(x + (size_t)gw * 64 + lane * 2);
    float2 og = make_float2(fmaf(dd, wx, dd * dd * xv.x),
                            fmaf(dd, wy, dd * dd * xv.y));
    float2 om = make_float2(mx * ci, my * ci);
    *(float2*)(outG + (size_t)gw * 64 + lane * 2) = og;
    *(float2*)(outM + (size_t)gw * 64 + lane * 2) = om;
}

__global__ void k_agg_dual2(const float* __restrict__ g1, const float* __restrict__ s1,
                            float* __restrict__ outG, float* __restrict__ outM, int n) {
    int gw   = (blockIdx.x * blockDim.x + threadIdx.x) >> 5;
    int lane = threadIdx.x & 31;
    if (gw >= n) return;
    int start = g_rowptr[gw];
    int cnt   = g_deg[gw];
    float wx = 0.f, wy = 0.f, mx = 0.f, my = 0.f;
    int e = 0;
    for (; e + 2 <= cnt; e += 2) {
        int i0 = g_edge[start + e];
        int i1 = g_edge[start + e + 1];
        float d0 = g_dinv[i0], d1 = g_dinv[i1];
        float2 a0 = *(const float2*)(g1 + (size_t)i0 * 64 + lane * 2);
        float2 a1 = *(const float2*)(g1 + (size_t)i1 * 64 + lane * 2);
        float2 b0 = *(const float2*)(s1 + (size_t)i0 * 64 + lane * 2);
        float2 b1 = *(const float2*)(s1 + (size_t)i1 * 64 + lane * 2);
        wx = fmaf(d0, a0.x, fmaf(d1, a1.x, wx));
        wy = fmaf(d0, a0.y, fmaf(d1, a1.y, wy));
        mx += b0.x + b1.x;
        my += b0.y + b1.y;
    }
    for (; e < cnt; e++) {
        int i0 = g_edge[start + e];
        float d0 = g_dinv[i0];
        float2 a0 = *(const float2*)(g1 + (size_t)i0 * 64 + lane * 2);
        float2 b0 = *(const float2*)(s1 + (size_t)i0 * 64 + lane * 2);
        wx = fmaf(d0, a0.x, wx);
        wy = fmaf(d0, a0.y, wy);
        mx += b0.x;
        my += b0.y;
    }
    float dd = g_dinv[gw];
    float ci = g_cinv[gw];
    float2 gsv = *(const float2*)(g1 + (size_t)gw * 64 + lane * 2);
    float2 og = make_float2(fmaf(dd, wx, dd * dd * gsv.x),
                            fmaf(dd, wy, dd * dd * gsv.y));
    float2 om = make_float2(mx * ci, my * ci);
    *(float2*)(outG + (size_t)gw * 64 + lane * 2) = og;
    *(float2*)(outM + (size_t)gw * 64 + lane * 2) = om;
}

// ---------------- GEMM: Y = act( Xa@Wa [+ Xb@Wb] + bias ), widths 64 --------
// 128 threads, 128-row tile, 8x8 thread tile, XOR-swizzled Xs (bank-conflict-free).
// LDS traffic = 1.0 B/FMA (crossbar/FMA balance point).
template <bool DUAL, bool RELU>
__global__ void __launch_bounds__(128, 2)
k_gemm(const float* __restrict__ Xa, const float* __restrict__ Wa,
       const float* __restrict__ Xb, const float* __restrict__ Wb,
       const float* __restrict__ bias, float* __restrict__ Y, int n) {
    constexpr int KT = DUAL ? 128 : 64;
    constexpr int KQ = KT / 4;
    extern __shared__ float sm[];
    float* Xs = sm;              // [128][KT], column-quads XOR-swizzled per 8-row group
    float* Ws = sm + 128 * KT;   // [KT][64]

    int tid  = threadIdx.x;
    int base = blockIdx.x * 128;

    for (int i = tid; i < KT * 16; i += 128) {
        int k = i >> 4, c = (i & 15) << 2;
        const float* wsrc = (DUAL && k >= 64) ? (Wb + (size_t)(k - 64) * 64 + c)
                                              : (Wa + (size_t)k * 64 + c);
        *(float4*)&Ws[k * 64 + c] = *(const float4*)wsrc;
    }
    for (int i = tid; i < 128 * KQ; i += 128) {
        int r  = i / KQ;
        int kq = i % KQ;
        int row = base + r;
        float4 v = make_float4(0.f, 0.f, 0.f, 0.f);
        if (row < n) {
            int k = kq * 4;
            const float* xsrc = (DUAL && k >= 64) ? (Xb + (size_t)row * 64 + (k - 64))
                                                  : (Xa + (size_t)row * 64 + k);
            v = *(const float4*)xsrc;
        }
        int sw = (r >> 3) & 7;
        *(float4*)&Xs[r * KT + ((kq ^ sw) << 2)] = v;
    }
    __syncthreads();

    int rg    = tid >> 3;   // 0..15 -> 8 rows each
    int cg    = tid & 7;    // 0..7  -> 8 cols each
    int rbase = rg * 8;
    int sw    = rg & 7;

    float acc[8][8];
#pragma unroll
    for (int q = 0; q < 8; q++)
#pragma unroll
        for (int c = 0; c < 8; c++) acc[q][c] = 0.f;

    for (int kc = 0; kc < KQ; kc++) {
        int k  = kc * 4;
        int pc = (kc ^ sw) << 2;
        float4 xv[8];
#pragma unroll
        for (int q = 0; q < 8; q++)
            xv[q] = *(const float4*)&Xs[(rbase + q) * KT + pc];
#pragma unroll
        for (int j = 0; j < 4; j++) {
            float4 w0 = *(const float4*)&Ws[(k + j) * 64 + cg * 8];
            float4 w1 = *(const float4*)&Ws[(k + j) * 64 + cg * 8 + 4];
#pragma unroll
            for (int q = 0; q < 8; q++) {
                float xs = (j == 0) ? xv[q].x : (j == 1) ? xv[q].y
                         : (j == 2) ? xv[q].z : xv[q].w;
                acc[q][0] = fmaf(xs, w0.x, acc[q][0]);
                acc[q][1] = fmaf(xs, w0.y, acc[q][1]);
                acc[q][2] = fmaf(xs, w0.z, acc[q][2]);
                acc[q][3] = fmaf(xs, w0.w, acc[q][3]);
                acc[q][4] = fmaf(xs, w1.x, acc[q][4]);
                acc[q][5] = fmaf(xs, w1.y, acc[q][5]);
                acc[q][6] = fmaf(xs, w1.z, acc[q][6]);
                acc[q][7] = fmaf(xs, w1.w, acc[q][7]);
            }
        }
    }

    float4 b0 = *(const float4*)&bias[cg * 8];
    float4 b1 = *(const float4*)&bias[cg * 8 + 4];
#pragma unroll
    for (int q = 0; q < 8; q++) {
        int row = base + rbase + q;
        if (row >= n) continue;
        float4 o0 = make_float4(acc[q][0] + b0.x, acc[q][1] + b0.y,
                                acc[q][2] + b0.z, acc[q][3] + b0.w);
        float4 o1 = make_float4(acc[q][4] + b1.x, acc[q][5] + b1.y,
                                acc[q][6] + b1.z, acc[q][7] + b1.w);
        if (RELU) {
            o0.x = fmaxf(o0.x, 0.f); o0.y = fmaxf(o0.y, 0.f);
            o0.z = fmaxf(o0.z, 0.f); o0.w = fmaxf(o0.w, 0.f);
            o1.x = fmaxf(o1.x, 0.f); o1.y = fmaxf(o1.y, 0.f);
            o1.z = fmaxf(o1.z, 0.f); o1.w = fmaxf(o1.w, 0.f);
        }
        *(float4*)&Y[(size_t)row * 64 + cg * 8]     = o0;
        *(float4*)&Y[(size_t)row * 64 + cg * 8 + 4] = o1;
    }
}

// ---------------- projection GEMM with fused per-branch LayerNorm -----------
__global__ void __launch_bounds__(128, 2)
k_proj(const float* __restrict__ G, const float* __restrict__ S,
       const float* __restrict__ gg, const float* __restrict__ gb,
       const float* __restrict__ sg, const float* __restrict__ sb,
       const float* __restrict__ W, const float* __restrict__ bias,
       float* __restrict__ Y, int n) {
    constexpr int KT = 128, KQ = 32;
    extern __shared__ float sm[];
    float* Xs  = sm;                 // [128][128] swizzled
    float* Ws  = sm + 128 * KT;      // [128][64]
    float* gam = Ws + 128 * 64;      // [128]
    float* bet = gam + 128;          // [128]

    int tid  = threadIdx.x;
    int base = blockIdx.x * 128;

    gam[tid] = (tid < 64) ? gg[tid] : sg[tid - 64];
    bet[tid] = (tid < 64) ? gb[tid] : sb[tid - 64];
    for (int i = tid; i < 128 * 16; i += 128) {
        int k = i >> 4, c = (i & 15) << 2;
        *(float4*)&Ws[k * 64 + c] = *(const float4*)(W + (size_t)k * 64 + c);
    }
    for (int i = tid; i < 128 * KQ; i += 128) {
        int r  = i / KQ;
        int kq = i % KQ;
        int row = base + r;
        float4 v = make_float4(0.f, 0.f, 0.f, 0.f);
        if (row < n) {
            int k = kq * 4;
            const float* xsrc = (k >= 64) ? (S + (size_t)row * 64 + (k - 64))
                                          : (G + (size_t)row * 64 + k);
            v = *(const float4*)xsrc;
        }
        int sw = (r >> 3) & 7;
        *(float4*)&Xs[r * KT + ((kq ^ sw) << 2)] = v;
    }
    __syncthreads();

    // LayerNorm in place: 256 tasks (row, half), 2 per thread. Swizzle-aware.
#pragma unroll
    for (int tt = 0; tt < 2; tt++) {
        int task = tid + tt * 128;
        int r    = task >> 1;
        int half = task & 1;
        int sw   = (r >> 3) & 7;
        float s = 0.f, q = 0.f;
#pragma unroll
        for (int c4 = 0; c4 < 16; c4++) {
            int pc = ((half * 16 + c4) ^ sw) << 2;
            float4 v = *(float4*)&Xs[r * KT + pc];
            s += v.x + v.y + v.z + v.w;
            q += v.x * v.x + v.y * v.y + v.z * v.z + v.w * v.w;
        }
        float mu  = s * (1.0f / 64.0f);
        float var = fmaxf(q * (1.0f / 64.0f) - mu * mu, 0.f);
        float rs  = rsqrtf(var + 1e-5f);
#pragma unroll
        for (int c4 = 0; c4 < 16; c4++) {
            int pc = ((half * 16 + c4) ^ sw) << 2;
            int gc = half * 64 + c4 * 4;
            float4 v = *(float4*)&Xs[r * KT + pc];
            v.x = (v.x - mu) * rs * gam[gc]     + bet[gc];
            v.y = (v.y - mu) * rs * gam[gc + 1] + bet[gc + 1];
            v.z = (v.z - mu) * rs * gam[gc + 2] + bet[gc + 2];
            v.w = (v.w - mu) * rs * gam[gc + 3] + bet[gc + 3];
            *(float4*)&Xs[r * KT + pc] = v;
        }
    }
    __syncthreads();

    int rg    = tid >> 3;
    int cg    = tid & 7;
    int rbase = rg * 8;
    int sw    = rg & 7;

    float acc[8][8];
#pragma unroll
    for (int q = 0; q < 8; q++)
#pragma unroll
        for (int c = 0; c < 8; c++) acc[q][c] = 0.f;

    for (int kc = 0; kc < KQ; kc++) {
        int k  = kc * 4;
        int pc = (kc ^ sw) << 2;
        float4 xv[8];
#pragma unroll
        for (int q = 0; q < 8; q++)
            xv[q] = *(const float4*)&Xs[(rbase + q) * KT + pc];
#pragma unroll
        for (int j = 0; j < 4; j++) {
            float4 w0 = *(const float4*)&Ws[(k + j) * 64 + cg * 8];
            float4 w1 = *(const float4*)&Ws[(k + j) * 64 + cg * 8 + 4];
#pragma unroll
            for (int q = 0; q < 8; q++) {
                float xs = (j == 0) ? xv[q].x : (j == 1) ? xv[q].y
                         : (j == 2) ? xv[q].z : xv[q].w;
                acc[q][0] = fmaf(xs, w0.x, acc[q][0]);
                acc[q][1] = fmaf(xs, w0.y, acc[q][1]);
                acc[q][2] = fmaf(xs, w0.z, acc[q][2]);
                acc[q][3] = fmaf(xs, w0.w, acc[q][3]);
                acc[q][4] = fmaf(xs, w1.x, acc[q][4]);
                acc[q][5] = fmaf(xs, w1.y, acc[q][5]);
                acc[q][6] = fmaf(xs, w1.z, acc[q][6]);
                acc[q][7] = fmaf(xs, w1.w, acc[q][7]);
            }
        }
    }

    float4 b0 = *(const float4*)&bias[cg * 8];
    float4 b1 = *(const float4*)&bias[cg * 8 + 4];
#pragma unroll
    for (int q = 0; q < 8; q++) {
        int row = base + rbase + q;
        if (row >= n) continue;
        float4 o0 = make_float4(acc[q][0] + b0.x, acc[q][1] + b0.y,
                                acc[q][2] + b0.z, acc[q][3] + b0.w);
        float4 o1 = make_float4(acc[q][4] + b1.x, acc[q][5] + b1.y,
                                acc[q][6] + b1.z, acc[q][7] + b1.w);
        *(float4*)&Y[(size_t)row * 64 + cg * 8]     = o0;
        *(float4*)&Y[(size_t)row * 64 + cg * 8 + 4] = o1;
    }
}

// ---------------- launcher ---------------------------------------------------
extern "C" void kernel_launch(void* const* d_in, const int* in_sizes, int n_in,
                              void* d_out, int out_size) {
    const float* x        = (const float*)d_in[0];
    const void*  ei       = d_in[1];                 // int64 or int32; auto-detected
    const float* gcn_w1   = (const float*)d_in[2];
    const float* gcn_b1   = (const float*)d_in[3];
    const float* gcn_w2   = (const float*)d_in[4];
    const float* gcn_b2   = (const float*)d_in[5];
    const float* sage_wl1 = (const float*)d_in[6];
    const float* sage_bl1 = (const float*)d_in[7];
    const float* sage_wr1 = (const float*)d_in[8];
    const float* sage_wl2 = (const float*)d_in[9];
    const float* sage_bl2 = (const float*)d_in[10];
    const float* sage_wr2 = (const float*)d_in[11];
    const float* gln_g    = (const float*)d_in[12];
    const float* gln_b    = (const float*)d_in[13];
    const float* sln_g    = (const float*)d_in[14];
    const float* sln_b    = (const float*)d_in[15];
    const float* proj_w   = (const float*)d_in[16];
    const float* proj_b   = (const float*)d_in[17];
    float*       out      = (float*)d_out;

    int n = in_sizes[0] / 64;
    int e = in_sizes[1] / 2;

    float* bufbase = nullptr;
    cudaGetSymbolAddress((void**)&bufbase, g_buf);
    float* B[6];
    for (int i = 0; i < 6; i++) B[i] = bufbase + (size_t)i * N_MAX * 64;

    const size_t sm1 = (size_t)(128 * 64 + 64 * 64) * 4;           // 49152
    const size_t sm2 = (size_t)(128 * 128 + 128 * 64) * 4;         // 98304
    const size_t smp = sm2 + 256 * 4;                              // 99328
    cudaFuncSetAttribute(k_gemm<false, true>,
                         cudaFuncAttributeMaxDynamicSharedMemorySize, (int)sm1);
    cudaFuncSetAttribute(k_gemm<false, false>,
                         cudaFuncAttributeMaxDynamicSharedMemorySize, (int)sm1);
    cudaFuncSetAttribute(k_gemm<true, true>,
                         cudaFuncAttributeMaxDynamicSharedMemorySize, (int)sm2);
    cudaFuncSetAttribute(k_gemm<true, false>,
                         cudaFuncAttributeMaxDynamicSharedMemorySize, (int)sm2);
    cudaFuncSetAttribute(k_proj,
                         cudaFuncAttributeMaxDynamicSharedMemorySize, (int)smp);

    int nb1k = (n + 1023) / 1024;
    int gb   = (n + 127) / 128;
    int ab   = (n + 7) / 8;       // warp-per-node blocks (256 thr)

    // CSR build (12 launches total)
    k_detzero<<<(n + 255) / 256, 256>>>(ei, e, n);
    k_count<<<(e + 255) / 256, 256>>>(ei, e, n);
    k_scan1<<<nb1k, 1024>>>(n);
    k_scan23<<<nb1k, 1024>>>(n, nb1k);
    k_scatter<<<(e + 255) / 256, 256>>>(ei, e, n);

    // Layer 1: fused dual aggregation over x, then the two layer-1 GEMMs
    k_agg_dual1<<<ab, 256>>>(x, B[0], B[1], n);                       // B0=GCN-agg(x), B1=mean(x)
    k_gemm<false, true><<<gb, 128, sm1>>>(B[0], gcn_w1, nullptr, nullptr, gcn_b1, B[2], n);  // g1
    k_gemm<true,  true><<<gb, 128, sm2>>>(B[1], sage_wl1, x, sage_wr1, sage_bl1, B[3], n);   // s1

    // Layer 2: fused dual aggregation over (g1, s1), then the two layer-2 GEMMs
    k_agg_dual2<<<ab, 256>>>(B[2], B[3], B[0], B[1], n);              // B0=GCN-agg(g1), B1=mean(s1)
    k_gemm<false, false><<<gb, 128, sm1>>>(B[0], gcn_w2, nullptr, nullptr, gcn_b2, B[4], n); // g2
    k_gemm<true,  false><<<gb, 128, sm2>>>(B[1], sage_wl2, B[3], sage_wr2, sage_bl2, B[5], n); // s2

    // Fused LayerNorm + concat projection
    k_proj<<<gb, 128, smp>>>(B[4], B[5], gln_g, gln_b, sln_g, sln_b,
                             proj_w, proj_b, out, n);
}

// round 11
// speedup vs baseline: 1.1109x; 1.1109x over previous
#include <cuda_runtime.h>
#include <cstdint>

#define N_MAX 100000
#define E_MAX 1250000

// ---------------- scratch (static device allocations; no runtime alloc) -----
__device__ int   g_is64;
__device__ int   g_deg[N_MAX];
__device__ int   g_incl[N_MAX];
__device__ int   g_rowptr[N_MAX];
__device__ int   g_cursor[N_MAX];
__device__ int   g_bsum[256];
__device__ float g_dinv[N_MAX];   // rsqrt(indeg+1)  (GCN)
__device__ float g_cinv[N_MAX];   // 1/max(indeg,1)  (SAGE mean)
__device__ int   g_edge[E_MAX];   // src index, bucketed by dst
__device__ float g_buf[6][(size_t)N_MAX * 64];

// ---------------- fused: zero degrees + edge-dtype detection ----------------
__global__ void k_detzero(const void* __restrict__ ei, int e, int n) {
    int i = blockIdx.x * blockDim.x + threadIdx.x;
    if (i < n) g_deg[i] = 0;
    if (blockIdx.x == 0) {
        __shared__ int bad;
        if (threadIdx.x == 0) bad = 0;
        __syncthreads();
        const long long* p = (const long long*)ei;
        int m = e < 2048 ? e : 2048;
        for (int j = threadIdx.x; j < m; j += blockDim.x) {
            long long v = p[j];
            if (v < 0 || v >= (long long)n) bad = 1;
        }
        __syncthreads();
        if (threadIdx.x == 0) g_is64 = bad ? 0 : 1;
    }
}

__device__ __forceinline__ int ld_idx(const void* __restrict__ ei, int is64,
                                      long long pos, int n) {
    long long v = is64 ? ((const long long*)ei)[pos]
                       : (long long)((const int*)ei)[pos];
    int s = (int)v;
    if ((unsigned)s >= (unsigned)n) s = 0;   // trap-safety clamp
    return s;
}

// ---------------- CSR build --------------------------------------------------
__global__ void k_count(const void* __restrict__ ei, int e, int n) {
    int i = blockIdx.x * blockDim.x + threadIdx.x;
    if (i >= e) return;
    int is64 = g_is64;
    int d = ld_idx(ei, is64, (long long)e + i, n);
    atomicAdd(&g_deg[d], 1);
}

__global__ void k_scan1(int n) {  // per-block inclusive scan (1024/block)
    __shared__ int sh[1024];
    int t = threadIdx.x;
    int i = blockIdx.x * 1024 + t;
    int v = (i < n) ? g_deg[i] : 0;
    sh[t] = v;
    __syncthreads();
    for (int off = 1; off < 1024; off <<= 1) {
        int add = (t >= off) ? sh[t - off] : 0;
        __syncthreads();
        sh[t] += add;
        __syncthreads();
    }
    if (i < n) g_incl[i] = sh[t];
    if (t == 1023) g_bsum[blockIdx.x] = sh[1023];
}

// fused scan2+scan3: every block redundantly scans the <=256 block sums in smem
__global__ void k_scan23(int n, int nb) {
    __shared__ int sh[256];
    __shared__ int orig[256];
    int t = threadIdx.x;
    if (t < 256) {
        int v = (t < nb) ? g_bsum[t] : 0;
        sh[t] = v;
        orig[t] = v;
    }
    __syncthreads();
    for (int off = 1; off < 256; off <<= 1) {
        int add = (t < 256 && t >= off) ? sh[t - off] : 0;
        __syncthreads();
        if (t < 256) sh[t] += add;
        __syncthreads();
    }
    int i = blockIdx.x * 1024 + t;
    if (i >= n) return;
    int boff = sh[blockIdx.x] - orig[blockIdx.x];  // exclusive prefix of this block
    int d  = g_deg[i];
    int rp = g_incl[i] - d + boff;
    g_rowptr[i] = rp;
    g_cursor[i] = rp;
    g_dinv[i] = rsqrtf((float)d + 1.0f);
    g_cinv[i] = 1.0f / fmaxf((float)d, 1.0f);
}

__global__ void k_scatter(const void* __restrict__ ei, int e, int n) {
    int i = blockIdx.x * blockDim.x + threadIdx.x;
    if (i >= e) return;
    int is64 = g_is64;
    int s = ld_idx(ei, is64, i, n);
    int d = ld_idx(ei, is64, (long long)e + i, n);
    int pos = atomicAdd(&g_cursor[d], 1);
    g_edge[pos] = s;
}

// ---------------- fused dual aggregations (warp per node, 2 feats/lane) -----
__global__ void k_agg_dual1(const float* __restrict__ x,
                            float* __restrict__ outG, float* __restrict__ outM, int n) {
    int gw   = (blockIdx.x * blockDim.x + threadIdx.x) >> 5;
    int lane = threadIdx.x & 31;
    if (gw >= n) return;
    int start = g_rowptr[gw];
    int cnt   = g_deg[gw];
    float wx = 0.f, wy = 0.f, mx = 0.f, my = 0.f;
    int src = (cnt > 0) ? g_edge[start] : 0;
    for (int e = 0; e < cnt; e++) {
        int cur = src;
        if (e + 1 < cnt) src = g_edge[start + e + 1];
        float ds = g_dinv[cur];
        float2 v = *(const float2*)(x + (size_t)cur * 64 + lane * 2);
        wx = fmaf(ds, v.x, wx);
        wy = fmaf(ds, v.y, wy);
        mx += v.x;
        my += v.y;
    }
    float dd = g_dinv[gw];
    float ci = g_cinv[gw];
    float2 xv = *(const float2*)(x + (size_t)gw * 64 + lane * 2);
    float2 og = make_float2(fmaf(dd, wx, dd * dd * xv.x),
                            fmaf(dd, wy, dd * dd * xv.y));
    float2 om = make_float2(mx * ci, my * ci);
    *(float2*)(outG + (size_t)gw * 64 + lane * 2) = og;
    *(float2*)(outM + (size_t)gw * 64 + lane * 2) = om;
}

__global__ void k_agg_dual2(const float* __restrict__ g1, const float* __restrict__ s1,
                            float* __restrict__ outG, float* __restrict__ outM, int n) {
    int gw   = (blockIdx.x * blockDim.x + threadIdx.x) >> 5;
    int lane = threadIdx.x & 31;
    if (gw >= n) return;
    int start = g_rowptr[gw];
    int cnt   = g_deg[gw];
    float wx = 0.f, wy = 0.f, mx = 0.f, my = 0.f;
    int src = (cnt > 0) ? g_edge[start] : 0;
    for (int e = 0; e < cnt; e++) {
        int cur = src;
        if (e + 1 < cnt) src = g_edge[start + e + 1];
        float ds = g_dinv[cur];
        float2 gv = *(const float2*)(g1 + (size_t)cur * 64 + lane * 2);
        float2 sv = *(const float2*)(s1 + (size_t)cur * 64 + lane * 2);
        wx = fmaf(ds, gv.x, wx);
        wy = fmaf(ds, gv.y, wy);
        mx += sv.x;
        my += sv.y;
    }
    float dd = g_dinv[gw];
    float ci = g_cinv[gw];
    float2 gsv = *(const float2*)(g1 + (size_t)gw * 64 + lane * 2);
    float2 og = make_float2(fmaf(dd, wx, dd * dd * gsv.x),
                            fmaf(dd, wy, dd * dd * gsv.y));
    float2 om = make_float2(mx * ci, my * ci);
    *(float2*)(outG + (size_t)gw * 64 + lane * 2) = og;
    *(float2*)(outM + (size_t)gw * 64 + lane * 2) = om;
}

// ---------------- GEMM: Y = act( Xa@Wa [+ Xb@Wb] + bias ), widths 64 --------
// Block: 256 threads, 128 rows. Thread tile: 4 rows x 8 cols.
// Row mapping rg + 32q -> intra-warp Xs rows adjacent (spacing KP === 4 mod 32)
// => conflict-free mainloop Xs loads.
template <bool DUAL, bool RELU>
__global__ void k_gemm(const float* __restrict__ Xa, const float* __restrict__ Wa,
                       const float* __restrict__ Xb, const float* __restrict__ Wb,
                       const float* __restrict__ bias, float* __restrict__ Y, int n) {
    constexpr int KT = DUAL ? 128 : 64;
    constexpr int KP = KT + 4;
    extern __shared__ float sm[];
    float* Xs = sm;              // [128][KP]
    float* Ws = sm + 128 * KP;   // [KT][64]

    int tid  = threadIdx.x;
    int base = blockIdx.x * 128;

    for (int i = tid; i < KT * 16; i += 256) {
        int k = i >> 4, c = (i & 15) << 2;
        const float* wsrc = (DUAL && k >= 64) ? (Wb + (size_t)(k - 64) * 64 + c)
                                              : (Wa + (size_t)k * 64 + c);
        *(float4*)&Ws[k * 64 + c] = *(const float4*)wsrc;
    }
    for (int i = tid; i < 128 * (KT / 4); i += 256) {
        int r  = i / (KT / 4);
        int kq = i % (KT / 4);
        int row = base + r;
        float4 v = make_float4(0.f, 0.f, 0.f, 0.f);
        if (row < n) {
            int k = kq * 4;
            const float* xsrc = (DUAL && k >= 64) ? (Xb + (size_t)row * 64 + (k - 64))
                                                  : (Xa + (size_t)row * 64 + k);
            v = *(const float4*)xsrc;
        }
        *(float4*)&Xs[r * KP + kq * 4] = v;
    }
    __syncthreads();

    int rg = tid >> 3;  // 0..31 -> rows rg + 32q
    int cg = tid & 7;   // 0..7

    float acc[4][8];
#pragma unroll
    for (int q = 0; q < 4; q++)
#pragma unroll
        for (int c = 0; c < 8; c++) acc[q][c] = 0.f;

    for (int k = 0; k < KT; k += 4) {
        float4 xv[4];
#pragma unroll
        for (int q = 0; q < 4; q++)
            xv[q] = *(const float4*)&Xs[(rg + 32 * q) * KP + k];
#pragma unroll
        for (int j = 0; j < 4; j++) {
            float4 w0 = *(const float4*)&Ws[(k + j) * 64 + cg * 8];
            float4 w1 = *(const float4*)&Ws[(k + j) * 64 + cg * 8 + 4];
#pragma unroll
            for (int q = 0; q < 4; q++) {
                float xs = (j == 0) ? xv[q].x : (j == 1) ? xv[q].y
                         : (j == 2) ? xv[q].z : xv[q].w;
                acc[q][0] = fmaf(xs, w0.x, acc[q][0]);
                acc[q][1] = fmaf(xs, w0.y, acc[q][1]);
                acc[q][2] = fmaf(xs, w0.z, acc[q][2]);
                acc[q][3] = fmaf(xs, w0.w, acc[q][3]);
                acc[q][4] = fmaf(xs, w1.x, acc[q][4]);
                acc[q][5] = fmaf(xs, w1.y, acc[q][5]);
                acc[q][6] = fmaf(xs, w1.z, acc[q][6]);
                acc[q][7] = fmaf(xs, w1.w, acc[q][7]);
            }
        }
    }

    float4 b0 = *(const float4*)&bias[cg * 8];
    float4 b1 = *(const float4*)&bias[cg * 8 + 4];
#pragma unroll
    for (int q = 0; q < 4; q++) {
        int row = base + rg + 32 * q;
        if (row >= n) continue;
        float4 o0 = make_float4(acc[q][0] + b0.x, acc[q][1] + b0.y,
                                acc[q][2] + b0.z, acc[q][3] + b0.w);
        float4 o1 = make_float4(acc[q][4] + b1.x, acc[q][5] + b1.y,
                                acc[q][6] + b1.z, acc[q][7] + b1.w);
        if (RELU) {
            o0.x = fmaxf(o0.x, 0.f); o0.y = fmaxf(o0.y, 0.f);
            o0.z = fmaxf(o0.z, 0.f); o0.w = fmaxf(o0.w, 0.f);
            o1.x = fmaxf(o1.x, 0.f); o1.y = fmaxf(o1.y, 0.f);
            o1.z = fmaxf(o1.z, 0.f); o1.w = fmaxf(o1.w, 0.f);
        }
        *(float4*)&Y[(size_t)row * 64 + cg * 8]     = o0;
        *(float4*)&Y[(size_t)row * 64 + cg * 8 + 4] = o1;
    }
}

// ---------------- projection GEMM with fused per-branch LayerNorm -----------
// out = [LN(g2)|LN(s2)] @ W(128x64) + bias.  LN applied in the shared tile.
__global__ void k_proj(const float* __restrict__ G, const float* __restrict__ S,
                       const float* __restrict__ gg, const float* __restrict__ gb,
                       const float* __restrict__ sg, const float* __restrict__ sb,
                       const float* __restrict__ W, const float* __restrict__ bias,
                       float* __restrict__ Y, int n) {
    constexpr int KT = 128, KP = 132;
    extern __shared__ float sm[];
    float* Xs  = sm;                       // [128][132]
    float* Ws  = sm + 128 * KP;            // [128][64]
    float* gam = Ws + 128 * 64;            // [128]
    float* bet = gam + 128;                // [128]

    int tid  = threadIdx.x;
    int base = blockIdx.x * 128;

    if (tid < 128) {
        gam[tid] = (tid < 64) ? gg[tid] : sg[tid - 64];
        bet[tid] = (tid < 64) ? gb[tid] : sb[tid - 64];
    }
    for (int i = tid; i < 128 * 16; i += 256) {
        int k = i >> 4, c = (i & 15) << 2;
        *(float4*)&Ws[k * 64 + c] = *(const float4*)(W + (size_t)k * 64 + c);
    }
    for (int i = tid; i < 128 * 32; i += 256) {
        int r  = i >> 5;
        int kq = i & 31;
        int row = base + r;
        float4 v = make_float4(0.f, 0.f, 0.f, 0.f);
        if (row < n) {
            int k = kq * 4;
            const float* xsrc = (k >= 64) ? (S + (size_t)row * 64 + (k - 64))
                                          : (G + (size_t)row * 64 + k);
            v = *(const float4*)xsrc;
        }
        *(float4*)&Xs[r * KP + kq * 4] = v;
    }
    __syncthreads();

    // LayerNorm in place: thread -> (row = tid/2, half = tid&1), 64 values each
    {
        int r    = tid >> 1;
        int half = tid & 1;
        float* p = &Xs[r * KP + half * 64];
        float s = 0.f, q = 0.f;
#pragma unroll
        for (int c = 0; c < 64; c += 4) {
            float4 v = *(float4*)&p[c];
            s += v.x + v.y + v.z + v.w;
            q += v.x * v.x + v.y * v.y + v.z * v.z + v.w * v.w;
        }
        float mu  = s * (1.0f / 64.0f);
        float var = fmaxf(q * (1.0f / 64.0f) - mu * mu, 0.f);
        float rs  = rsqrtf(var + 1e-5f);
        const float* gm = &gam[half * 64];
        const float* bt = &bet[half * 64];
#pragma unroll
        for (int c = 0; c < 64; c += 4) {
            float4 v = *(float4*)&p[c];
            v.x = (v.x - mu) * rs * gm[c]     + bt[c];
            v.y = (v.y - mu) * rs * gm[c + 1] + bt[c + 1];
            v.z = (v.z - mu) * rs * gm[c + 2] + bt[c + 2];
            v.w = (v.w - mu) * rs * gm[c + 3] + bt[c + 3];
            *(float4*)&p[c] = v;
        }
    }
    __syncthreads();

    int rg = tid >> 3;
    int cg = tid & 7;

    float acc[4][8];
#pragma unroll
    for (int q = 0; q < 4; q++)
#pragma unroll
        for (int c = 0; c < 8; c++) acc[q][c] = 0.f;

    for (int k = 0; k < KT; k += 4) {
        float4 xv[4];
#pragma unroll
        for (int q = 0; q < 4; q++)
            xv[q] = *(const float4*)&Xs[(rg + 32 * q) * KP + k];
#pragma unroll
        for (int j = 0; j < 4; j++) {
            float4 w0 = *(const float4*)&Ws[(k + j) * 64 + cg * 8];
            float4 w1 = *(const float4*)&Ws[(k + j) * 64 + cg * 8 + 4];
#pragma unroll
            for (int q = 0; q < 4; q++) {
                float xs = (j == 0) ? xv[q].x : (j == 1) ? xv[q].y
                         : (j == 2) ? xv[q].z : xv[q].w;
                acc[q][0] = fmaf(xs, w0.x, acc[q][0]);
                acc[q][1] = fmaf(xs, w0.y, acc[q][1]);
                acc[q][2] = fmaf(xs, w0.z, acc[q][2]);
                acc[q][3] = fmaf(xs, w0.w, acc[q][3]);
                acc[q][4] = fmaf(xs, w1.x, acc[q][4]);
                acc[q][5] = fmaf(xs, w1.y, acc[q][5]);
                acc[q][6] = fmaf(xs, w1.z, acc[q][6]);
                acc[q][7] = fmaf(xs, w1.w, acc[q][7]);
            }
        }
    }

    float4 b0 = *(const float4*)&bias[cg * 8];
    float4 b1 = *(const float4*)&bias[cg * 8 + 4];
#pragma unroll
    for (int q = 0; q < 4; q++) {
        int row = base + rg + 32 * q;
        if (row >= n) continue;
        float4 o0 = make_float4(acc[q][0] + b0.x, acc[q][1] + b0.y,
                                acc[q][2] + b0.z, acc[q][3] + b0.w);
        float4 o1 = make_float4(acc[q][4] + b1.x, acc[q][5] + b1.y,
                                acc[q][6] + b1.z, acc[q][7] + b1.w);
        *(float4*)&Y[(size_t)row * 64 + cg * 8]     = o0;
        *(float4*)&Y[(size_t)row * 64 + cg * 8 + 4] = o1;
    }
}

// ---------------- launcher ---------------------------------------------------
extern "C" void kernel_launch(void* const* d_in, const int* in_sizes, int n_in,
                              void* d_out, int out_size) {
    const float* x        = (const float*)d_in[0];
    const void*  ei       = d_in[1];                 // int64 or int32; auto-detected
    const float* gcn_w1   = (const float*)d_in[2];
    const float* gcn_b1   = (const float*)d_in[3];
    const float* gcn_w2   = (const float*)d_in[4];
    const float* gcn_b2   = (const float*)d_in[5];
    const float* sage_wl1 = (const float*)d_in[6];
    const float* sage_bl1 = (const float*)d_in[7];
    const float* sage_wr1 = (const float*)d_in[8];
    const float* sage_wl2 = (const float*)d_in[9];
    const float* sage_bl2 = (const float*)d_in[10];
    const float* sage_wr2 = (const float*)d_in[11];
    const float* gln_g    = (const float*)d_in[12];
    const float* gln_b    = (const float*)d_in[13];
    const float* sln_g    = (const float*)d_in[14];
    const float* sln_b    = (const float*)d_in[15];
    const float* proj_w   = (const float*)d_in[16];
    const float* proj_b   = (const float*)d_in[17];
    float*       out      = (float*)d_out;

    int n = in_sizes[0] / 64;
    int e = in_sizes[1] / 2;

    float* bufbase = nullptr;
    cudaGetSymbolAddress((void**)&bufbase, g_buf);
    float* B[6];
    for (int i = 0; i < 6; i++) B[i] = bufbase + (size_t)i * N_MAX * 64;

    const size_t sm1 = (size_t)(128 * 68 + 64 * 64) * 4;           // 51200
    const size_t sm2 = (size_t)(128 * 132 + 128 * 64) * 4;         // 100352
    const size_t smp = (size_t)(128 * 132 + 128 * 64 + 256) * 4;   // 101376
    cudaFuncSetAttribute(k_gemm<false, true>,
                         cudaFuncAttributeMaxDynamicSharedMemorySize, (int)sm1);
    cudaFuncSetAttribute(k_gemm<false, false>,
                         cudaFuncAttributeMaxDynamicSharedMemorySize, (int)sm1);
    cudaFuncSetAttribute(k_gemm<true, true>,
                         cudaFuncAttributeMaxDynamicSharedMemorySize, (int)sm2);
    cudaFuncSetAttribute(k_gemm<true, false>,
                         cudaFuncAttributeMaxDynamicSharedMemorySize, (int)sm2);
    cudaFuncSetAttribute(k_proj,
                         cudaFuncAttributeMaxDynamicSharedMemorySize, (int)smp);

    int nb1k = (n + 1023) / 1024;
    int gb   = (n + 127) / 128;
    int ab   = (n + 7) / 8;       // warp-per-node blocks (256 thr)

    // CSR build
    k_detzero<<<(n + 255) / 256, 256>>>(ei, e, n);
    k_count<<<(e + 255) / 256, 256>>>(ei, e, n);
    k_scan1<<<nb1k, 1024>>>(n);
    k_scan23<<<nb1k, 1024>>>(n, nb1k);
    k_scatter<<<(e + 255) / 256, 256>>>(ei, e, n);

    // Layer 1: fused dual aggregation over x, then the two layer-1 GEMMs
    k_agg_dual1<<<ab, 256>>>(x, B[0], B[1], n);                       // B0=GCN-agg(x), B1=mean(x)
    k_gemm<false, true><<<gb, 256, sm1>>>(B[0], gcn_w1, nullptr, nullptr, gcn_b1, B[2], n);  // g1
    k_gemm<true,  true><<<gb, 256, sm2>>>(B[1], sage_wl1, x, sage_wr1, sage_bl1, B[3], n);   // s1

    // Layer 2: fused dual aggregation over (g1, s1), then the two layer-2 GEMMs
    k_agg_dual2<<<ab, 256>>>(B[2], B[3], B[0], B[1], n);              // B0=GCN-agg(g1), B1=mean(s1)
    k_gemm<false, false><<<gb, 256, sm1>>>(B[0], gcn_w2, nullptr, nullptr, gcn_b2, B[4], n); // g2
    k_gemm<true,  false><<<gb, 256, sm2>>>(B[1], sage_wl2, B[3], sage_wr2, sage_bl2, B[5], n); // s2

    // Fused LayerNorm + concat projection
    k_proj<<<gb, 256, smp>>>(B[4], B[5], gln_g, gln_b, sln_g, sln_b,
                             proj_w, proj_b, out, n);
}

// round 12
// speedup vs baseline: 1.5155x; 1.3642x over previous
#include <cuda_runtime.h>
#include <cuda_bf16.h>
#include <cstdint>

#define N_MAX 100000
#define E_MAX 1250000

// ---------------- scratch (static device allocations; no runtime alloc) -----
__device__ int   g_is64;
__device__ int   g_deg[N_MAX];
__device__ int   g_incl[N_MAX];
__device__ int   g_rowptr[N_MAX];
__device__ int   g_cursor[N_MAX];
__device__ int   g_bsum[256];
__device__ float g_dinv[N_MAX];   // rsqrt(indeg+1)  (GCN)
__device__ float g_cinv[N_MAX];   // 1/max(indeg,1)  (SAGE mean)
__device__ int   g_edge[E_MAX];   // src index, bucketed by dst
__device__ float g_buf[6][(size_t)N_MAX * 64];

// ---------------- fused: zero degrees + edge-dtype detection ----------------
__global__ void k_detzero(const void* __restrict__ ei, int e, int n) {
    int i = blockIdx.x * blockDim.x + threadIdx.x;
    if (i < n) g_deg[i] = 0;
    if (blockIdx.x == 0) {
        __shared__ int bad;
        if (threadIdx.x == 0) bad = 0;
        __syncthreads();
        const long long* p = (const long long*)ei;
        int m = e < 2048 ? e : 2048;
        for (int j = threadIdx.x; j < m; j += blockDim.x) {
            long long v = p[j];
            if (v < 0 || v >= (long long)n) bad = 1;
        }
        __syncthreads();
        if (threadIdx.x == 0) g_is64 = bad ? 0 : 1;
    }
}

__device__ __forceinline__ int ld_idx(const void* __restrict__ ei, int is64,
                                      long long pos, int n) {
    long long v = is64 ? ((const long long*)ei)[pos]
                       : (long long)((const int*)ei)[pos];
    int s = (int)v;
    if ((unsigned)s >= (unsigned)n) s = 0;   // trap-safety clamp
    return s;
}

// ---------------- CSR build --------------------------------------------------
__global__ void k_count(const void* __restrict__ ei, int e, int n) {
    int i = blockIdx.x * blockDim.x + threadIdx.x;
    if (i >= e) return;
    int is64 = g_is64;
    int d = ld_idx(ei, is64, (long long)e + i, n);
    atomicAdd(&g_deg[d], 1);
}

__global__ void k_scan1(int n) {  // per-block inclusive scan (1024/block)
    __shared__ int sh[1024];
    int t = threadIdx.x;
    int i = blockIdx.x * 1024 + t;
    int v = (i < n) ? g_deg[i] : 0;
    sh[t] = v;
    __syncthreads();
    for (int off = 1; off < 1024; off <<= 1) {
        int add = (t >= off) ? sh[t - off] : 0;
        __syncthreads();
        sh[t] += add;
        __syncthreads();
    }
    if (i < n) g_incl[i] = sh[t];
    if (t == 1023) g_bsum[blockIdx.x] = sh[1023];
}

// fused scan2+scan3: every block redundantly scans the <=256 block sums in smem
__global__ void k_scan23(int n, int nb) {
    __shared__ int sh[256];
    __shared__ int orig[256];
    int t = threadIdx.x;
    if (t < 256) {
        int v = (t < nb) ? g_bsum[t] : 0;
        sh[t] = v;
        orig[t] = v;
    }
    __syncthreads();
    for (int off = 1; off < 256; off <<= 1) {
        int add = (t < 256 && t >= off) ? sh[t - off] : 0;
        __syncthreads();
        if (t < 256) sh[t] += add;
        __syncthreads();
    }
    int i = blockIdx.x * 1024 + t;
    if (i >= n) return;
    int boff = sh[blockIdx.x] - orig[blockIdx.x];  // exclusive prefix of this block
    int d  = g_deg[i];
    int rp = g_incl[i] - d + boff;
    g_rowptr[i] = rp;
    g_cursor[i] = rp;
    g_dinv[i] = rsqrtf((float)d + 1.0f);
    g_cinv[i] = 1.0f / fmaxf((float)d, 1.0f);
}

__global__ void k_scatter(const void* __restrict__ ei, int e, int n) {
    int i = blockIdx.x * blockDim.x + threadIdx.x;
    if (i >= e) return;
    int is64 = g_is64;
    int s = ld_idx(ei, is64, i, n);
    int d = ld_idx(ei, is64, (long long)e + i, n);
    int pos = atomicAdd(&g_cursor[d], 1);
    g_edge[pos] = s;
}

// ---------------- fused dual aggregations (warp per node, 2 feats/lane) -----
__global__ void k_agg_dual1(const float* __restrict__ x,
                            float* __restrict__ outG, float* __restrict__ outM, int n) {
    int gw   = (blockIdx.x * blockDim.x + threadIdx.x) >> 5;
    int lane = threadIdx.x & 31;
    if (gw >= n) return;
    int start = g_rowptr[gw];
    int cnt   = g_deg[gw];
    float wx = 0.f, wy = 0.f, mx = 0.f, my = 0.f;
    int src = (cnt > 0) ? g_edge[start] : 0;
    for (int e = 0; e < cnt; e++) {
        int cur = src;
        if (e + 1 < cnt) src = g_edge[start + e + 1];
        float ds = g_dinv[cur];
        float2 v = *(const float2*)(x + (size_t)cur * 64 + lane * 2);
        wx = fmaf(ds, v.x, wx);
        wy = fmaf(ds, v.y, wy);
        mx += v.x;
        my += v.y;
    }
    float dd = g_dinv[gw];
    float ci = g_cinv[gw];
    float2 xv = *(const float2*)(x + (size_t)gw * 64 + lane * 2);
    float2 og = make_float2(fmaf(dd, wx, dd * dd * xv.x),
                            fmaf(dd, wy, dd * dd * xv.y));
    float2 om = make_float2(mx * ci, my * ci);
    *(float2*)(outG + (size_t)gw * 64 + lane * 2) = og;
    *(float2*)(outM + (size_t)gw * 64 + lane * 2) = om;
}

__global__ void k_agg_dual2(const float* __restrict__ g1, const float* __restrict__ s1,
                            float* __restrict__ outG, float* __restrict__ outM, int n) {
    int gw   = (blockIdx.x * blockDim.x + threadIdx.x) >> 5;
    int lane = threadIdx.x & 31;
    if (gw >= n) return;
    int start = g_rowptr[gw];
    int cnt   = g_deg[gw];
    float wx = 0.f, wy = 0.f, mx = 0.f, my = 0.f;
    int src = (cnt > 0) ? g_edge[start] : 0;
    for (int e = 0; e < cnt; e++) {
        int cur = src;
        if (e + 1 < cnt) src = g_edge[start + e + 1];
        float ds = g_dinv[cur];
        float2 gv = *(const float2*)(g1 + (size_t)cur * 64 + lane * 2);
        float2 sv = *(const float2*)(s1 + (size_t)cur * 64 + lane * 2);
        wx = fmaf(ds, gv.x, wx);
        wy = fmaf(ds, gv.y, wy);
        mx += sv.x;
        my += sv.y;
    }
    float dd = g_dinv[gw];
    float ci = g_cinv[gw];
    float2 gsv = *(const float2*)(g1 + (size_t)gw * 64 + lane * 2);
    float2 og = make_float2(fmaf(dd, wx, dd * dd * gsv.x),
                            fmaf(dd, wy, dd * dd * gsv.y));
    float2 om = make_float2(mx * ci, my * ci);
    *(float2*)(outG + (size_t)gw * 64 + lane * 2) = og;
    *(float2*)(outM + (size_t)gw * 64 + lane * 2) = om;
}

// ---------------- tensor-core GEMM via split-bf16 (3-term) -------------------
// Y = act( Xa@Wa [+ Xb@Wb] + bias ),  X: [n][64 or 128] fp32, W: [K][64] fp32.
// x = hi + lo (bf16 pair); A@B ~= Ahi Bhi + Ahi Blo + Alo Bhi, fp32 accumulate.
// Block: 256 thr (8 warps); tile 128 rows x 64 cols; warp -> 16 rows.

__device__ __forceinline__ void mma_bf16(float* c,
                                         uint32_t a0, uint32_t a1, uint32_t a2, uint32_t a3,
                                         uint32_t b0, uint32_t b1) {
    asm volatile(
        "mma.sync.aligned.m16n8k16.row.col.f32.bf16.bf16.f32 "
        "{%0,%1,%2,%3}, {%4,%5,%6,%7}, {%8,%9}, {%0,%1,%2,%3};\n"
        : "+f"(c[0]), "+f"(c[1]), "+f"(c[2]), "+f"(c[3])
        : "r"(a0), "r"(a1), "r"(a2), "r"(a3), "r"(b0), "r"(b1));
}

__device__ __forceinline__ void split_pack(float x, float y, uint32_t& hi, uint32_t& lo) {
    __nv_bfloat162 h = __floats2bfloat162_rn(x, y);
    __nv_bfloat162 l = __floats2bfloat162_rn(x - __bfloat162float(h.x),
                                             y - __bfloat162float(h.y));
    hi = *(uint32_t*)&h;
    lo = *(uint32_t*)&l;
}

template <bool DUAL, bool RELU>
__global__ void k_gemm(const float* __restrict__ Xa, const float* __restrict__ Wa,
                       const float* __restrict__ Xb, const float* __restrict__ Wb,
                       const float* __restrict__ bias, float* __restrict__ Y, int n) {
    constexpr int KT  = DUAL ? 128 : 64;
    constexpr int KP  = KT + 8;    // bf16 elems per smem row (pitch === 4 words mod 32)
    constexpr int KPW = KP / 2;    // 32-bit words per row
    extern __shared__ uint32_t smu[];
    uint32_t* Ahi = smu;
    uint32_t* Alo = Ahi + 128 * KPW;
    uint32_t* Bhi = Alo + 128 * KPW;
    uint32_t* Blo = Bhi + 64 * KPW;

    int tid  = threadIdx.x;
    int base = blockIdx.x * 128;

    // stage W transposed: Bt[n][k], split hi/lo (bf16 scalar stores; tiny)
    __nv_bfloat16* BhiH = (__nv_bfloat16*)Bhi;
    __nv_bfloat16* BloH = (__nv_bfloat16*)Blo;
    for (int i = tid; i < KT * 16; i += 256) {
        int k = i >> 4, c = (i & 15) << 2;
        const float* wsrc = (DUAL && k >= 64) ? (Wb + (size_t)(k - 64) * 64 + c)
                                              : (Wa + (size_t)k * 64 + c);
        float4 v = *(const float4*)wsrc;
        float vv[4] = {v.x, v.y, v.z, v.w};
#pragma unroll
        for (int j = 0; j < 4; j++) {
            __nv_bfloat16 h = __float2bfloat16_rn(vv[j]);
            BhiH[(c + j) * KP + k] = h;
            BloH[(c + j) * KP + k] = __float2bfloat16_rn(vv[j] - __bfloat162float(h));
        }
    }
    // stage X, split hi/lo
    constexpr int KQ4 = KT / 4;
    for (int i = tid; i < 128 * KQ4; i += 256) {
        int r  = i / KQ4;
        int kq = i % KQ4;
        int row = base + r;
        float4 v = make_float4(0.f, 0.f, 0.f, 0.f);
        if (row < n) {
            int k = kq * 4;
            const float* xsrc = (DUAL && k >= 64) ? (Xb + (size_t)row * 64 + (k - 64))
                                                  : (Xa + (size_t)row * 64 + k);
            v = *(const float4*)xsrc;
        }
        uint32_t h0, l0, h1, l1;
        split_pack(v.x, v.y, h0, l0);
        split_pack(v.z, v.w, h1, l1);
        int wo = r * KPW + kq * 2;
        Ahi[wo]     = h0;
        Ahi[wo + 1] = h1;
        Alo[wo]     = l0;
        Alo[wo + 1] = l1;
    }
    __syncthreads();

    int warp  = tid >> 5;
    int lane  = tid & 31;
    int tq    = lane >> 2;   // 0..7
    int tc    = lane & 3;    // 0..3
    int rbase = warp * 16;

    float acc[8][4];
#pragma unroll
    for (int nt = 0; nt < 8; nt++)
#pragma unroll
        for (int c = 0; c < 4; c++) acc[nt][c] = 0.f;

#pragma unroll
    for (int kk = 0; kk < KT / 16; kk++) {
        int colw = kk * 8 + tc;
        int ra = (rbase + tq) * KPW + colw;
        int rb = ra + 8 * KPW;
        uint32_t ah0 = Ahi[ra], ah1 = Ahi[rb], ah2 = Ahi[ra + 4], ah3 = Ahi[rb + 4];
        uint32_t al0 = Alo[ra], al1 = Alo[rb], al2 = Alo[ra + 4], al3 = Alo[rb + 4];
#pragma unroll
        for (int nt = 0; nt < 8; nt++) {
            int nb = (nt * 8 + tq) * KPW + colw;
            uint32_t bh0 = Bhi[nb], bh1 = Bhi[nb + 4];
            uint32_t bl0 = Blo[nb], bl1 = Blo[nb + 4];
            mma_bf16(acc[nt], ah0, ah1, ah2, ah3, bh0, bh1);
            mma_bf16(acc[nt], ah0, ah1, ah2, ah3, bl0, bl1);
            mma_bf16(acc[nt], al0, al1, al2, al3, bh0, bh1);
        }
    }

    int r0 = base + rbase + tq;
    int r1 = r0 + 8;
#pragma unroll
    for (int nt = 0; nt < 8; nt++) {
        int col = nt * 8 + 2 * tc;
        float2 bv = *(const float2*)&bias[col];
        float2 o0 = make_float2(acc[nt][0] + bv.x, acc[nt][1] + bv.y);
        float2 o1 = make_float2(acc[nt][2] + bv.x, acc[nt][3] + bv.y);
        if (RELU) {
            o0.x = fmaxf(o0.x, 0.f); o0.y = fmaxf(o0.y, 0.f);
            o1.x = fmaxf(o1.x, 0.f); o1.y = fmaxf(o1.y, 0.f);
        }
        if (r0 < n) *(float2*)&Y[(size_t)r0 * 64 + col] = o0;
        if (r1 < n) *(float2*)&Y[(size_t)r1 * 64 + col] = o1;
    }
}

// ---------------- projection GEMM with fused per-branch LayerNorm -----------
// out = [LN(g2)|LN(s2)] @ W(128x64) + bias.  LN during staging (warp per row),
// then split-bf16 tensor-core mainloop (K=128).
__global__ void k_proj(const float* __restrict__ G, const float* __restrict__ S,
                       const float* __restrict__ gg, const float* __restrict__ gb,
                       const float* __restrict__ sg, const float* __restrict__ sb,
                       const float* __restrict__ W, const float* __restrict__ bias,
                       float* __restrict__ Y, int n) {
    constexpr int KT = 128, KP = 136, KPW = 68;
    extern __shared__ uint32_t smu[];
    uint32_t* Ahi = smu;
    uint32_t* Alo = Ahi + 128 * KPW;
    uint32_t* Bhi = Alo + 128 * KPW;
    uint32_t* Blo = Bhi + 64 * KPW;

    int tid  = threadIdx.x;
    int warp = tid >> 5;
    int lane = tid & 31;
    int base = blockIdx.x * 128;

    // stage W (proj_w 128x64) transposed, split hi/lo
    __nv_bfloat16* BhiH = (__nv_bfloat16*)Bhi;
    __nv_bfloat16* BloH = (__nv_bfloat16*)Blo;
    for (int i = tid; i < 128 * 16; i += 256) {
        int k = i >> 4, c = (i & 15) << 2;
        float4 v = *(const float4*)(W + (size_t)k * 64 + c);
        float vv[4] = {v.x, v.y, v.z, v.w};
#pragma unroll
        for (int j = 0; j < 4; j++) {
            __nv_bfloat16 h = __float2bfloat16_rn(vv[j]);
            BhiH[(c + j) * KP + k] = h;
            BloH[(c + j) * KP + k] = __float2bfloat16_rn(vv[j] - __bfloat162float(h));
        }
    }

    // stage X with LN: warp per row, 16 rows per warp
    float2 ggv = *(const float2*)&gg[lane * 2];
    float2 gbv = *(const float2*)&gb[lane * 2];
    float2 sgv = *(const float2*)&sg[lane * 2];
    float2 sbv = *(const float2*)&sb[lane * 2];
    for (int it = 0; it < 16; it++) {
        int r   = warp * 16 + it;
        int row = base + r;
        float2 gv = make_float2(0.f, 0.f), sv = make_float2(0.f, 0.f);
        if (row < n) {
            gv = *(const float2*)(G + (size_t)row * 64 + lane * 2);
            sv = *(const float2*)(S + (size_t)row * 64 + lane * 2);
        }
        float sgm = gv.x + gv.y, qg = gv.x * gv.x + gv.y * gv.y;
        float ssm = sv.x + sv.y, qs = sv.x * sv.x + sv.y * sv.y;
#pragma unroll
        for (int o = 16; o > 0; o >>= 1) {
            sgm += __shfl_xor_sync(0xffffffffu, sgm, o);
            qg  += __shfl_xor_sync(0xffffffffu, qg, o);
            ssm += __shfl_xor_sync(0xffffffffu, ssm, o);
            qs  += __shfl_xor_sync(0xffffffffu, qs, o);
        }
        float mug  = sgm * (1.0f / 64.0f);
        float varg = fmaxf(qg * (1.0f / 64.0f) - mug * mug, 0.f);
        float rg   = rsqrtf(varg + 1e-5f);
        float mus  = ssm * (1.0f / 64.0f);
        float vars = fmaxf(qs * (1.0f / 64.0f) - mus * mus, 0.f);
        float rs   = rsqrtf(vars + 1e-5f);
        float ogx = (gv.x - mug) * rg * ggv.x + gbv.x;
        float ogy = (gv.y - mug) * rg * ggv.y + gbv.y;
        float osx = (sv.x - mus) * rs * sgv.x + sbv.x;
        float osy = (sv.y - mus) * rs * sgv.y + sbv.y;
        uint32_t h, l;
        split_pack(ogx, ogy, h, l);
        Ahi[r * KPW + lane] = h;
        Alo[r * KPW + lane] = l;
        split_pack(osx, osy, h, l);
        Ahi[r * KPW + 32 + lane] = h;
        Alo[r * KPW + 32 + lane] = l;
    }
    __syncthreads();

    int tq    = lane >> 2;
    int tc    = lane & 3;
    int rbase = warp * 16;

    float acc[8][4];
#pragma unroll
    for (int nt = 0; nt < 8; nt++)
#pragma unroll
        for (int c = 0; c < 4; c++) acc[nt][c] = 0.f;

#pragma unroll
    for (int kk = 0; kk < KT / 16; kk++) {
        int colw = kk * 8 + tc;
        int ra = (rbase + tq) * KPW + colw;
        int rb = ra + 8 * KPW;
        uint32_t ah0 = Ahi[ra], ah1 = Ahi[rb], ah2 = Ahi[ra + 4], ah3 = Ahi[rb + 4];
        uint32_t al0 = Alo[ra], al1 = Alo[rb], al2 = Alo[ra + 4], al3 = Alo[rb + 4];
#pragma unroll
        for (int nt = 0; nt < 8; nt++) {
            int nb = (nt * 8 + tq) * KPW + colw;
            uint32_t bh0 = Bhi[nb], bh1 = Bhi[nb + 4];
            uint32_t bl0 = Blo[nb], bl1 = Blo[nb + 4];
            mma_bf16(acc[nt], ah0, ah1, ah2, ah3, bh0, bh1);
            mma_bf16(acc[nt], ah0, ah1, ah2, ah3, bl0, bl1);
            mma_bf16(acc[nt], al0, al1, al2, al3, bh0, bh1);
        }
    }

    int r0 = base + rbase + tq;
    int r1 = r0 + 8;
#pragma unroll
    for (int nt = 0; nt < 8; nt++) {
        int col = nt * 8 + 2 * tc;
        float2 bv = *(const float2*)&bias[col];
        float2 o0 = make_float2(acc[nt][0] + bv.x, acc[nt][1] + bv.y);
        float2 o1 = make_float2(acc[nt][2] + bv.x, acc[nt][3] + bv.y);
        if (r0 < n) *(float2*)&Y[(size_t)r0 * 64 + col] = o0;
        if (r1 < n) *(float2*)&Y[(size_t)r1 * 64 + col] = o1;
    }
}

// ---------------- launcher ---------------------------------------------------
extern "C" void kernel_launch(void* const* d_in, const int* in_sizes, int n_in,
                              void* d_out, int out_size) {
    const float* x        = (const float*)d_in[0];
    const void*  ei       = d_in[1];                 // int64 or int32; auto-detected
    const float* gcn_w1   = (const float*)d_in[2];
    const float* gcn_b1   = (const float*)d_in[3];
    const float* gcn_w2   = (const float*)d_in[4];
    const float* gcn_b2   = (const float*)d_in[5];
    const float* sage_wl1 = (const float*)d_in[6];
    const float* sage_bl1 = (const float*)d_in[7];
    const float* sage_wr1 = (const float*)d_in[8];
    const float* sage_wl2 = (const float*)d_in[9];
    const float* sage_bl2 = (const float*)d_in[10];
    const float* sage_wr2 = (const float*)d_in[11];
    const float* gln_g    = (const float*)d_in[12];
    const float* gln_b    = (const float*)d_in[13];
    const float* sln_g    = (const float*)d_in[14];
    const float* sln_b    = (const float*)d_in[15];
    const float* proj_w   = (const float*)d_in[16];
    const float* proj_b   = (const float*)d_in[17];
    float*       out      = (float*)d_out;

    int n = in_sizes[0] / 64;
    int e = in_sizes[1] / 2;

    float* bufbase = nullptr;
    cudaGetSymbolAddress((void**)&bufbase, g_buf);
    float* B[6];
    for (int i = 0; i < 6; i++) B[i] = bufbase + (size_t)i * N_MAX * 64;

    // smem: (Ahi+Alo)[128][KP] bf16 + (Bhi+Blo)[64][KP] bf16
    const size_t sm1 = (size_t)(128 + 64) * 72 * 2 * 2;    //  55296 (K=64)
    const size_t sm2 = (size_t)(128 + 64) * 136 * 2 * 2;   // 104448 (K=128)
    cudaFuncSetAttribute(k_gemm<false, true>,
                         cudaFuncAttributeMaxDynamicSharedMemorySize, (int)sm1);
    cudaFuncSetAttribute(k_gemm<false, false>,
                         cudaFuncAttributeMaxDynamicSharedMemorySize, (int)sm1);
    cudaFuncSetAttribute(k_gemm<true, true>,
                         cudaFuncAttributeMaxDynamicSharedMemorySize, (int)sm2);
    cudaFuncSetAttribute(k_gemm<true, false>,
                         cudaFuncAttributeMaxDynamicSharedMemorySize, (int)sm2);
    cudaFuncSetAttribute(k_proj,
                         cudaFuncAttributeMaxDynamicSharedMemorySize, (int)sm2);

    int nb1k = (n + 1023) / 1024;
    int gb   = (n + 127) / 128;
    int ab   = (n + 7) / 8;       // warp-per-node blocks (256 thr)

    // CSR build
    k_detzero<<<(n + 255) / 256, 256>>>(ei, e, n);
    k_count<<<(e + 255) / 256, 256>>>(ei, e, n);
    k_scan1<<<nb1k, 1024>>>(n);
    k_scan23<<<nb1k, 1024>>>(n, nb1k);
    k_scatter<<<(e + 255) / 256, 256>>>(ei, e, n);

    // Layer 1: fused dual aggregation over x, then the two layer-1 GEMMs
    k_agg_dual1<<<ab, 256>>>(x, B[0], B[1], n);                       // B0=GCN-agg(x), B1=mean(x)
    k_gemm<false, true><<<gb, 256, sm1>>>(B[0], gcn_w1, nullptr, nullptr, gcn_b1, B[2], n);  // g1
    k_gemm<true,  true><<<gb, 256, sm2>>>(B[1], sage_wl1, x, sage_wr1, sage_bl1, B[3], n);   // s1

    // Layer 2: fused dual aggregation over (g1, s1), then the two layer-2 GEMMs
    k_agg_dual2<<<ab, 256>>>(B[2], B[3], B[0], B[1], n);              // B0=GCN-agg(g1), B1=mean(s1)
    k_gemm<false, false><<<gb, 256, sm1>>>(B[0], gcn_w2, nullptr, nullptr, gcn_b2, B[4], n); // g2
    k_gemm<true,  false><<<gb, 256, sm2>>>(B[1], sage_wl2, B[3], sage_wr2, sage_bl2, B[5], n); // s2

    // Fused LayerNorm + concat projection (tensor-core)
    k_proj<<<gb, 256, sm2>>>(B[4], B[5], gln_g, gln_b, sln_g, sln_b,
                             proj_w, proj_b, out, n);
}

// round 13
// speedup vs baseline: 1.5812x; 1.0434x over previous
#include <cuda_runtime.h>
#include <cuda_bf16.h>
#include <cuda_fp16.h>
#include <cstdint>

#define N_MAX 100000
#define E_MAX 1250000

// ---------------- scratch (static device allocations; no runtime alloc) -----
__device__ int    g_is64;
__device__ int    g_deg[N_MAX];
__device__ int    g_incl[N_MAX];
__device__ int    g_rowptr[N_MAX];
__device__ int    g_cursor[N_MAX];
__device__ int    g_bsum[256];
__device__ float  g_dinv[N_MAX];   // rsqrt(indeg+1)  (GCN)
__device__ float  g_cinv[N_MAX];   // 1/max(indeg,1)  (SAGE mean)
__device__ int    g_edge[E_MAX];   // src index, bucketed by dst
__device__ float  g_buf[6][(size_t)N_MAX * 64];
__device__ __half g_half[3][(size_t)N_MAX * 64];   // xh, g1h, s1h

// ---------------- fused: zero degrees + x->fp16 + dtype detection ------------
__global__ void k_prep(const void* __restrict__ ei, const float* __restrict__ x,
                       __half* __restrict__ xh, int e, int n) {
    int i = blockIdx.x * blockDim.x + threadIdx.x;
    if (i < n) g_deg[i] = 0;
    int total = n * 16;   // float4 quads
    if (i < total) {
        float4 v = ((const float4*)x)[i];
        __half2 h0 = __floats2half2_rn(v.x, v.y);
        __half2 h1 = __floats2half2_rn(v.z, v.w);
        ((__half2*)xh)[i * 2]     = h0;
        ((__half2*)xh)[i * 2 + 1] = h1;
    }
    if (blockIdx.x == 0) {
        __shared__ int bad;
        if (threadIdx.x == 0) bad = 0;
        __syncthreads();
        const long long* p = (const long long*)ei;
        int m = e < 2048 ? e : 2048;
        for (int j = threadIdx.x; j < m; j += blockDim.x) {
            long long v = p[j];
            if (v < 0 || v >= (long long)n) bad = 1;
        }
        __syncthreads();
        if (threadIdx.x == 0) g_is64 = bad ? 0 : 1;
    }
}

__device__ __forceinline__ int ld_idx(const void* __restrict__ ei, int is64,
                                      long long pos, int n) {
    long long v = is64 ? ((const long long*)ei)[pos]
                       : (long long)((const int*)ei)[pos];
    int s = (int)v;
    if ((unsigned)s >= (unsigned)n) s = 0;   // trap-safety clamp
    return s;
}

// ---------------- CSR build --------------------------------------------------
__global__ void k_count(const void* __restrict__ ei, int e, int n) {
    int i = blockIdx.x * blockDim.x + threadIdx.x;
    if (i >= e) return;
    int is64 = g_is64;
    int d = ld_idx(ei, is64, (long long)e + i, n);
    atomicAdd(&g_deg[d], 1);
}

__global__ void k_scan1(int n) {  // per-block inclusive scan (1024/block)
    __shared__ int sh[1024];
    int t = threadIdx.x;
    int i = blockIdx.x * 1024 + t;
    int v = (i < n) ? g_deg[i] : 0;
    sh[t] = v;
    __syncthreads();
    for (int off = 1; off < 1024; off <<= 1) {
        int add = (t >= off) ? sh[t - off] : 0;
        __syncthreads();
        sh[t] += add;
        __syncthreads();
    }
    if (i < n) g_incl[i] = sh[t];
    if (t == 1023) g_bsum[blockIdx.x] = sh[1023];
}

// fused scan2+scan3: every block redundantly scans the <=256 block sums in smem
__global__ void k_scan23(int n, int nb) {
    __shared__ int sh[256];
    __shared__ int orig[256];
    int t = threadIdx.x;
    if (t < 256) {
        int v = (t < nb) ? g_bsum[t] : 0;
        sh[t] = v;
        orig[t] = v;
    }
    __syncthreads();
    for (int off = 1; off < 256; off <<= 1) {
        int add = (t < 256 && t >= off) ? sh[t - off] : 0;
        __syncthreads();
        if (t < 256) sh[t] += add;
        __syncthreads();
    }
    int i = blockIdx.x * 1024 + t;
    if (i >= n) return;
    int boff = sh[blockIdx.x] - orig[blockIdx.x];  // exclusive prefix of this block
    int d  = g_deg[i];
    int rp = g_incl[i] - d + boff;
    g_rowptr[i] = rp;
    g_cursor[i] = rp;
    g_dinv[i] = rsqrtf((float)d + 1.0f);
    g_cinv[i] = 1.0f / fmaxf((float)d, 1.0f);
}

__global__ void k_scatter(const void* __restrict__ ei, int e, int n) {
    int i = blockIdx.x * blockDim.x + threadIdx.x;
    if (i >= e) return;
    int is64 = g_is64;
    int s = ld_idx(ei, is64, i, n);
    int d = ld_idx(ei, is64, (long long)e + i, n);
    int pos = atomicAdd(&g_cursor[d], 1);
    g_edge[pos] = s;
}

// ---------------- fused dual aggregations (warp per node, 2 feats/lane) -----
// fp16 feature rows (128 B): lane loads half2, accumulates fp32.
__global__ void k_agg_dual1(const __half* __restrict__ xh,
                            float* __restrict__ outG, float* __restrict__ outM, int n) {
    int gw   = (blockIdx.x * blockDim.x + threadIdx.x) >> 5;
    int lane = threadIdx.x & 31;
    if (gw >= n) return;
    int start = g_rowptr[gw];
    int cnt   = g_deg[gw];
    float wx = 0.f, wy = 0.f, mx = 0.f, my = 0.f;
    int src = (cnt > 0) ? g_edge[start] : 0;
    for (int e = 0; e < cnt; e++) {
        int cur = src;
        if (e + 1 < cnt) src = g_edge[start + e + 1];
        float ds = g_dinv[cur];
        float2 v = __half22float2(*(const __half2*)(xh + (size_t)cur * 64 + lane * 2));
        wx = fmaf(ds, v.x, wx);
        wy = fmaf(ds, v.y, wy);
        mx += v.x;
        my += v.y;
    }
    float dd = g_dinv[gw];
    float ci = g_cinv[gw];
    float2 xv = __half22float2(*(const __half2*)(xh + (size_t)gw * 64 + lane * 2));
    float2 og = make_float2(fmaf(dd, wx, dd * dd * xv.x),
                            fmaf(dd, wy, dd * dd * xv.y));
    float2 om = make_float2(mx * ci, my * ci);
    *(float2*)(outG + (size_t)gw * 64 + lane * 2) = og;
    *(float2*)(outM + (size_t)gw * 64 + lane * 2) = om;
}

__global__ void k_agg_dual2(const __half* __restrict__ g1h, const __half* __restrict__ s1h,
                            float* __restrict__ outG, float* __restrict__ outM, int n) {
    int gw   = (blockIdx.x * blockDim.x + threadIdx.x) >> 5;
    int lane = threadIdx.x & 31;
    if (gw >= n) return;
    int start = g_rowptr[gw];
    int cnt   = g_deg[gw];
    float wx = 0.f, wy = 0.f, mx = 0.f, my = 0.f;
    int src = (cnt > 0) ? g_edge[start] : 0;
    for (int e = 0; e < cnt; e++) {
        int cur = src;
        if (e + 1 < cnt) src = g_edge[start + e + 1];
        float ds = g_dinv[cur];
        float2 gv = __half22float2(*(const __half2*)(g1h + (size_t)cur * 64 + lane * 2));
        float2 sv = __half22float2(*(const __half2*)(s1h + (size_t)cur * 64 + lane * 2));
        wx = fmaf(ds, gv.x, wx);
        wy = fmaf(ds, gv.y, wy);
        mx += sv.x;
        my += sv.y;
    }
    float dd = g_dinv[gw];
    float ci = g_cinv[gw];
    float2 gsv = __half22float2(*(const __half2*)(g1h + (size_t)gw * 64 + lane * 2));
    float2 og = make_float2(fmaf(dd, wx, dd * dd * gsv.x),
                            fmaf(dd, wy, dd * dd * gsv.y));
    float2 om = make_float2(mx * ci, my * ci);
    *(float2*)(outG + (size_t)gw * 64 + lane * 2) = og;
    *(float2*)(outM + (size_t)gw * 64 + lane * 2) = om;
}

// ---------------- tensor-core GEMM via split-bf16 (3-term) -------------------
__device__ __forceinline__ void mma_bf16(float* c,
                                         uint32_t a0, uint32_t a1, uint32_t a2, uint32_t a3,
                                         uint32_t b0, uint32_t b1) {
    asm volatile(
        "mma.sync.aligned.m16n8k16.row.col.f32.bf16.bf16.f32 "
        "{%0,%1,%2,%3}, {%4,%5,%6,%7}, {%8,%9}, {%0,%1,%2,%3};\n"
        : "+f"(c[0]), "+f"(c[1]), "+f"(c[2]), "+f"(c[3])
        : "r"(a0), "r"(a1), "r"(a2), "r"(a3), "r"(b0), "r"(b1));
}

__device__ __forceinline__ void split_pack(float x, float y, uint32_t& hi, uint32_t& lo) {
    __nv_bfloat162 h = __floats2bfloat162_rn(x, y);
    __nv_bfloat162 l = __floats2bfloat162_rn(x - __bfloat162float(h.x),
                                             y - __bfloat162float(h.y));
    hi = *(uint32_t*)&h;
    lo = *(uint32_t*)&l;
}

// Y = act( Xa@Wa [+ Xb@Wb] + bias ).  Xa fp32; Xb fp32 or fp16; Y fp32 or fp16.
template <bool DUAL, bool RELU, bool XB_HALF, bool OUT_HALF>
__global__ void k_gemm(const float* __restrict__ Xa, const float* __restrict__ Wa,
                       const void* __restrict__ Xb, const float* __restrict__ Wb,
                       const float* __restrict__ bias, void* __restrict__ Yv, int n) {
    constexpr int KT  = DUAL ? 128 : 64;
    constexpr int KP  = KT + 8;
    constexpr int KPW = KP / 2;
    extern __shared__ uint32_t smu[];
    uint32_t* Ahi = smu;
    uint32_t* Alo = Ahi + 128 * KPW;
    uint32_t* Bhi = Alo + 128 * KPW;
    uint32_t* Blo = Bhi + 64 * KPW;

    int tid  = threadIdx.x;
    int base = blockIdx.x * 128;

    __nv_bfloat16* BhiH = (__nv_bfloat16*)Bhi;
    __nv_bfloat16* BloH = (__nv_bfloat16*)Blo;
    for (int i = tid; i < KT * 16; i += 256) {
        int k = i >> 4, c = (i & 15) << 2;
        const float* wsrc = (DUAL && k >= 64) ? (Wb + (size_t)(k - 64) * 64 + c)
                                              : (Wa + (size_t)k * 64 + c);
        float4 v = *(const float4*)wsrc;
        float vv[4] = {v.x, v.y, v.z, v.w};
#pragma unroll
        for (int j = 0; j < 4; j++) {
            __nv_bfloat16 h = __float2bfloat16_rn(vv[j]);
            BhiH[(c + j) * KP + k] = h;
            BloH[(c + j) * KP + k] = __float2bfloat16_rn(vv[j] - __bfloat162float(h));
        }
    }
    constexpr int KQ4 = KT / 4;
    for (int i = tid; i < 128 * KQ4; i += 256) {
        int r  = i / KQ4;
        int kq = i % KQ4;
        int row = base + r;
        float4 v = make_float4(0.f, 0.f, 0.f, 0.f);
        if (row < n) {
            int k = kq * 4;
            if (DUAL && k >= 64) {
                if (XB_HALF) {
                    const __half* xb = (const __half*)Xb + (size_t)row * 64 + (k - 64);
                    float2 fa = __half22float2(*(const __half2*)xb);
                    float2 fb = __half22float2(*(const __half2*)(xb + 2));
                    v = make_float4(fa.x, fa.y, fb.x, fb.y);
                } else {
                    v = *(const float4*)((const float*)Xb + (size_t)row * 64 + (k - 64));
                }
            } else {
                v = *(const float4*)(Xa + (size_t)row * 64 + k);
            }
        }
        uint32_t h0, l0, h1, l1;
        split_pack(v.x, v.y, h0, l0);
        split_pack(v.z, v.w, h1, l1);
        int wo = r * KPW + kq * 2;
        Ahi[wo]     = h0;
        Ahi[wo + 1] = h1;
        Alo[wo]     = l0;
        Alo[wo + 1] = l1;
    }
    __syncthreads();

    int warp  = tid >> 5;
    int lane  = tid & 31;
    int tq    = lane >> 2;
    int tc    = lane & 3;
    int rbase = warp * 16;

    float acc[8][4];
#pragma unroll
    for (int nt = 0; nt < 8; nt++)
#pragma unroll
        for (int c = 0; c < 4; c++) acc[nt][c] = 0.f;

#pragma unroll
    for (int kk = 0; kk < KT / 16; kk++) {
        int colw = kk * 8 + tc;
        int ra = (rbase + tq) * KPW + colw;
        int rb = ra + 8 * KPW;
        uint32_t ah0 = Ahi[ra], ah1 = Ahi[rb], ah2 = Ahi[ra + 4], ah3 = Ahi[rb + 4];
        uint32_t al0 = Alo[ra], al1 = Alo[rb], al2 = Alo[ra + 4], al3 = Alo[rb + 4];
#pragma unroll
        for (int nt = 0; nt < 8; nt++) {
            int nb = (nt * 8 + tq) * KPW + colw;
            uint32_t bh0 = Bhi[nb], bh1 = Bhi[nb + 4];
            uint32_t bl0 = Blo[nb], bl1 = Blo[nb + 4];
            mma_bf16(acc[nt], ah0, ah1, ah2, ah3, bh0, bh1);
            mma_bf16(acc[nt], ah0, ah1, ah2, ah3, bl0, bl1);
            mma_bf16(acc[nt], al0, al1, al2, al3, bh0, bh1);
        }
    }

    int r0 = base + rbase + tq;
    int r1 = r0 + 8;
#pragma unroll
    for (int nt = 0; nt < 8; nt++) {
        int col = nt * 8 + 2 * tc;
        float2 bv = *(const float2*)&bias[col];
        float2 o0 = make_float2(acc[nt][0] + bv.x, acc[nt][1] + bv.y);
        float2 o1 = make_float2(acc[nt][2] + bv.x, acc[nt][3] + bv.y);
        if (RELU) {
            o0.x = fmaxf(o0.x, 0.f); o0.y = fmaxf(o0.y, 0.f);
            o1.x = fmaxf(o1.x, 0.f); o1.y = fmaxf(o1.y, 0.f);
        }
        if (OUT_HALF) {
            __half* Y = (__half*)Yv;
            if (r0 < n) *(__half2*)&Y[(size_t)r0 * 64 + col] = __floats2half2_rn(o0.x, o0.y);
            if (r1 < n) *(__half2*)&Y[(size_t)r1 * 64 + col] = __floats2half2_rn(o1.x, o1.y);
        } else {
            float* Y = (float*)Yv;
            if (r0 < n) *(float2*)&Y[(size_t)r0 * 64 + col] = o0;
            if (r1 < n) *(float2*)&Y[(size_t)r1 * 64 + col] = o1;
        }
    }
}

// ---------------- projection GEMM with fused per-branch LayerNorm -----------
__global__ void k_proj(const float* __restrict__ G, const float* __restrict__ S,
                       const float* __restrict__ gg, const float* __restrict__ gb,
                       const float* __restrict__ sg, const float* __restrict__ sb,
                       const float* __restrict__ W, const float* __restrict__ bias,
                       float* __restrict__ Y, int n) {
    constexpr int KT = 128, KP = 136, KPW = 68;
    extern __shared__ uint32_t smu[];
    uint32_t* Ahi = smu;
    uint32_t* Alo = Ahi + 128 * KPW;
    uint32_t* Bhi = Alo + 128 * KPW;
    uint32_t* Blo = Bhi + 64 * KPW;

    int tid  = threadIdx.x;
    int warp = tid >> 5;
    int lane = tid & 31;
    int base = blockIdx.x * 128;

    __nv_bfloat16* BhiH = (__nv_bfloat16*)Bhi;
    __nv_bfloat16* BloH = (__nv_bfloat16*)Blo;
    for (int i = tid; i < 128 * 16; i += 256) {
        int k = i >> 4, c = (i & 15) << 2;
        float4 v = *(const float4*)(W + (size_t)k * 64 + c);
        float vv[4] = {v.x, v.y, v.z, v.w};
#pragma unroll
        for (int j = 0; j < 4; j++) {
            __nv_bfloat16 h = __float2bfloat16_rn(vv[j]);
            BhiH[(c + j) * KP + k] = h;
            BloH[(c + j) * KP + k] = __float2bfloat16_rn(vv[j] - __bfloat162float(h));
        }
    }

    float2 ggv = *(const float2*)&gg[lane * 2];
    float2 gbv = *(const float2*)&gb[lane * 2];
    float2 sgv = *(const float2*)&sg[lane * 2];
    float2 sbv = *(const float2*)&sb[lane * 2];
    for (int it = 0; it < 16; it++) {
        int r   = warp * 16 + it;
        int row = base + r;
        float2 gv = make_float2(0.f, 0.f), sv = make_float2(0.f, 0.f);
        if (row < n) {
            gv = *(const float2*)(G + (size_t)row * 64 + lane * 2);
            sv = *(const float2*)(S + (size_t)row * 64 + lane * 2);
        }
        float sgm = gv.x + gv.y, qg = gv.x * gv.x + gv.y * gv.y;
        float ssm = sv.x + sv.y, qs = sv.x * sv.x + sv.y * sv.y;
#pragma unroll
        for (int o = 16; o > 0; o >>= 1) {
            sgm += __shfl_xor_sync(0xffffffffu, sgm, o);
            qg  += __shfl_xor_sync(0xffffffffu, qg, o);
            ssm += __shfl_xor_sync(0xffffffffu, ssm, o);
            qs  += __shfl_xor_sync(0xffffffffu, qs, o);
        }
        float mug  = sgm * (1.0f / 64.0f);
        float varg = fmaxf(qg * (1.0f / 64.0f) - mug * mug, 0.f);
        float rg   = rsqrtf(varg + 1e-5f);
        float mus  = ssm * (1.0f / 64.0f);
        float vars = fmaxf(qs * (1.0f / 64.0f) - mus * mus, 0.f);
        float rs   = rsqrtf(vars + 1e-5f);
        float ogx = (gv.x - mug) * rg * ggv.x + gbv.x;
        float ogy = (gv.y - mug) * rg * ggv.y + gbv.y;
        float osx = (sv.x - mus) * rs * sgv.x + sbv.x;
        float osy = (sv.y - mus) * rs * sgv.y + sbv.y;
        uint32_t h, l;
        split_pack(ogx, ogy, h, l);
        Ahi[r * KPW + lane] = h;
        Alo[r * KPW + lane] = l;
        split_pack(osx, osy, h, l);
        Ahi[r * KPW + 32 + lane] = h;
        Alo[r * KPW + 32 + lane] = l;
    }
    __syncthreads();

    int tq    = lane >> 2;
    int tc    = lane & 3;
    int rbase = warp * 16;

    float acc[8][4];
#pragma unroll
    for (int nt = 0; nt < 8; nt++)
#pragma unroll
        for (int c = 0; c < 4; c++) acc[nt][c] = 0.f;

#pragma unroll
    for (int kk = 0; kk < KT / 16; kk++) {
        int colw = kk * 8 + tc;
        int ra = (rbase + tq) * KPW + colw;
        int rb = ra + 8 * KPW;
        uint32_t ah0 = Ahi[ra], ah1 = Ahi[rb], ah2 = Ahi[ra + 4], ah3 = Ahi[rb + 4];
        uint32_t al0 = Alo[ra], al1 = Alo[rb], al2 = Alo[ra + 4], al3 = Alo[rb + 4];
#pragma unroll
        for (int nt = 0; nt < 8; nt++) {
            int nb = (nt * 8 + tq) * KPW + colw;
            uint32_t bh0 = Bhi[nb], bh1 = Bhi[nb + 4];
            uint32_t bl0 = Blo[nb], bl1 = Blo[nb + 4];
            mma_bf16(acc[nt], ah0, ah1, ah2, ah3, bh0, bh1);
            mma_bf16(acc[nt], ah0, ah1, ah2, ah3, bl0, bl1);
            mma_bf16(acc[nt], al0, al1, al2, al3, bh0, bh1);
        }
    }

    int r0 = base + rbase + tq;
    int r1 = r0 + 8;
#pragma unroll
    for (int nt = 0; nt < 8; nt++) {
        int col = nt * 8 + 2 * tc;
        float2 bv = *(const float2*)&bias[col];
        float2 o0 = make_float2(acc[nt][0] + bv.x, acc[nt][1] + bv.y);
        float2 o1 = make_float2(acc[nt][2] + bv.x, acc[nt][3] + bv.y);
        if (r0 < n) *(float2*)&Y[(size_t)r0 * 64 + col] = o0;
        if (r1 < n) *(float2*)&Y[(size_t)r1 * 64 + col] = o1;
    }
}

// ---------------- launcher ---------------------------------------------------
extern "C" void kernel_launch(void* const* d_in, const int* in_sizes, int n_in,
                              void* d_out, int out_size) {
    const float* x        = (const float*)d_in[0];
    const void*  ei       = d_in[1];                 // int64 or int32; auto-detected
    const float* gcn_w1   = (const float*)d_in[2];
    const float* gcn_b1   = (const float*)d_in[3];
    const float* gcn_w2   = (const float*)d_in[4];
    const float* gcn_b2   = (const float*)d_in[5];
    const float* sage_wl1 = (const float*)d_in[6];
    const float* sage_bl1 = (const float*)d_in[7];
    const float* sage_wr1 = (const float*)d_in[8];
    const float* sage_wl2 = (const float*)d_in[9];
    const float* sage_bl2 = (const float*)d_in[10];
    const float* sage_wr2 = (const float*)d_in[11];
    const float* gln_g    = (const float*)d_in[12];
    const float* gln_b    = (const float*)d_in[13];
    const float* sln_g    = (const float*)d_in[14];
    const float* sln_b    = (const float*)d_in[15];
    const float* proj_w   = (const float*)d_in[16];
    const float* proj_b   = (const float*)d_in[17];
    float*       out      = (float*)d_out;

    int n = in_sizes[0] / 64;
    int e = in_sizes[1] / 2;

    float* bufbase = nullptr;
    cudaGetSymbolAddress((void**)&bufbase, g_buf);
    float* B[6];
    for (int i = 0; i < 6; i++) B[i] = bufbase + (size_t)i * N_MAX * 64;
    __half* halfbase = nullptr;
    cudaGetSymbolAddress((void**)&halfbase, g_half);
    __half* xh  = halfbase;
    __half* g1h = halfbase + (size_t)N_MAX * 64;
    __half* s1h = halfbase + (size_t)2 * N_MAX * 64;

    const size_t sm1 = (size_t)(128 + 64) * 72 * 2 * 2;    //  55296 (K=64)
    const size_t sm2 = (size_t)(128 + 64) * 136 * 2 * 2;   // 104448 (K=128)
    cudaFuncSetAttribute(k_gemm<false, true, false, true>,
                         cudaFuncAttributeMaxDynamicSharedMemorySize, (int)sm1);
    cudaFuncSetAttribute(k_gemm<true, true, false, true>,
                         cudaFuncAttributeMaxDynamicSharedMemorySize, (int)sm2);
    cudaFuncSetAttribute(k_gemm<false, false, false, false>,
                         cudaFuncAttributeMaxDynamicSharedMemorySize, (int)sm1);
    cudaFuncSetAttribute(k_gemm<true, false, true, false>,
                         cudaFuncAttributeMaxDynamicSharedMemorySize, (int)sm2);
    cudaFuncSetAttribute(k_proj,
                         cudaFuncAttributeMaxDynamicSharedMemorySize, (int)sm2);

    int nb1k = (n + 1023) / 1024;
    int gb   = (n + 127) / 128;
    int ab   = (n + 7) / 8;       // warp-per-node blocks (256 thr)

    // CSR build + x fp16 conversion
    k_prep<<<(n * 16 + 255) / 256, 256>>>(ei, x, xh, e, n);
    k_count<<<(e + 255) / 256, 256>>>(ei, e, n);
    k_scan1<<<nb1k, 1024>>>(n);
    k_scan23<<<nb1k, 1024>>>(n, nb1k);
    k_scatter<<<(e + 255) / 256, 256>>>(ei, e, n);

    // Layer 1: fused dual aggregation over xh, then the two layer-1 GEMMs (fp16 out)
    k_agg_dual1<<<ab, 256>>>(xh, B[0], B[1], n);                      // B0=GCN-agg, B1=mean
    k_gemm<false, true, false, true><<<gb, 256, sm1>>>(B[0], gcn_w1, nullptr, nullptr, gcn_b1, g1h, n);
    k_gemm<true,  true, false, true><<<gb, 256, sm2>>>(B[1], sage_wl1, x, sage_wr1, sage_bl1, s1h, n);

    // Layer 2: fused dual aggregation over (g1h, s1h), then the two layer-2 GEMMs
    k_agg_dual2<<<ab, 256>>>(g1h, s1h, B[0], B[1], n);                // B0=GCN-agg, B1=mean
    k_gemm<false, false, false, false><<<gb, 256, sm1>>>(B[0], gcn_w2, nullptr, nullptr, gcn_b2, B[4], n);
    k_gemm<true,  false, true,  false><<<gb, 256, sm2>>>(B[1], sage_wl2, s1h, sage_wr2, sage_bl2, B[5], n);

    // Fused LayerNorm + concat projection (tensor-core)
    k_proj<<<gb, 256, sm2>>>(B[4], B[5], gln_g, gln_b, sln_g, sln_b,
                             proj_w, proj_b, out, n);
}